// round 1
// baseline (speedup 1.0000x reference)
#include <cuda_runtime.h>

#define EPSF     1.1920928955078125e-07f
#define LOG2E    1.4426950408889634f
#define NSAMP    2000
#define NPAD     2048
#define Y0F      0.9999f
#define NROWS    65536
#define FULLMASK 0xffffffffu

// Row-independent grid tables. g_tab[j] packs two grid points:
// (atanh_x[2j], c1[2j], atanh_x[2j+1], c1[2j+1]). Padded to 2048 with c1=0
// so padded points contribute exactly 0 probability.
__device__ float4 g_tab[NPAD / 2];
__device__ float  g_grid[NPAD];

__global__ void init_tables_kernel() {
    int j = blockIdx.x * blockDim.x + threadIdx.x;  // 0..1023
    if (j >= NPAD / 2) return;
    const float step = 2.0f * Y0F / 1999.0f;
    float4 v;
    float g0, g1;

    int i = 2 * j;
    if (i < NSAMP) {
        // mimic numpy/jax linspace: start + i*step, endpoint forced exact
        float x = (i == NSAMP - 1) ? Y0F
                                   : __fadd_rn(__fmul_rn((float)i, step), -Y0F);
        v.x = 0.5f * logf((1.0f + x) / (1.0f - x) + EPSF);
        v.y = 1.0f / (1.0f - x * x);
        g0 = x;
    } else { v.x = 0.0f; v.y = 0.0f; g0 = Y0F; }

    i = 2 * j + 1;
    if (i < NSAMP) {
        float x = (i == NSAMP - 1) ? Y0F
                                   : __fadd_rn(__fmul_rn((float)i, step), -Y0F);
        v.z = 0.5f * logf((1.0f + x) / (1.0f - x) + EPSF);
        v.w = 1.0f / (1.0f - x * x);
        g1 = x;
    } else { v.z = 0.0f; v.w = 0.0f; g1 = Y0F; }

    g_tab[j] = v;
    g_grid[2 * j]     = g0;
    g_grid[2 * j + 1] = g1;
}

// One warp per row. Lane l owns contiguous points [64l, 64l+64).
__global__ __launch_bounds__(256, 8) void sample_kernel(
    const float* __restrict__ mean,
    const float* __restrict__ stdv,
    const float* __restrict__ uni,
    float* __restrict__ out)
{
    const int lane = threadIdx.x & 31;
    const int warp = threadIdx.x >> 5;
    const int row  = blockIdx.x * 8 + warp;

    const float mu = __ldg(mean + row);
    const float sg = __ldg(stdv + row) + EPSF;
    const float u  = __ldg(uni + row);
    // fold 1/(-2 sigma^2) and log2(e) into one constant: exp(a) = exp2(a*log2e)
    const float k2 = (-0.5f * LOG2E) / (sg * sg);

    // ---- Phase 1: per-lane segment sums of un-normalized probs ----
    float s = 0.0f;
    const float4* tp = g_tab + lane * 32;  // 32 float4 = 64 points per lane
    #pragma unroll 8
    for (int j = 0; j < 32; ++j) {
        float4 v = __ldg(tp + j);
        float t0 = v.x - mu;
        float t1 = v.z - mu;
        float p0 = v.y * exp2f(t0 * t0 * k2);
        float p1 = v.w * exp2f(t1 * t1 * k2);
        s += p0;
        s += p1;
    }

    // inclusive warp scan of lane sums
    float incl = s;
    #pragma unroll
    for (int o = 1; o < 32; o <<= 1) {
        float t = __shfl_up_sync(FULLMASK, incl, o);
        if (lane >= o) incl += t;
    }
    const float total = __shfl_sync(FULLMASK, incl, 31);
    const float excl  = incl - s;

    const float invnorm = rsqrtf(6.283185307179586f * sg * sg);
    const float denom   = __fmaf_rn(invnorm, total, EPSF);   // S_norm + EPS
    const float Traw    = u * denom / invnorm;               // threshold in raw space

    // ---- Phase 2: locate crossing segment, then exact index ----
    unsigned m = __ballot_sync(FULLMASK, incl > Traw);
    int idx;
    if (m == 0u) {
        // No crossing in raw space: either u >= cdf_last (reference argmax -> 0)
        // or a raw-space rounding artifact with u ~ 1 (reference -> last index).
        float Snorm = invnorm * total;
        float cl = Snorm / (Snorm + EPSF);   // reference's cdf[last]
        idx = (u < cl) ? (NSAMP - 1) : 0;
    } else {
        const int L = __ffs(m) - 1;
        const float base = __shfl_sync(FULLMASK, excl, L);
        float T2 = Traw - base;
        const int base_i = L * 64;
        idx = -1;
        for (int sub = 0; sub < 64 && idx < 0; sub += 32) {
            int i = base_i + sub + lane;
            float4 q = __ldg(&g_tab[i >> 1]);
            float ax = (i & 1) ? q.z : q.x;
            float cc = (i & 1) ? q.w : q.y;
            float t = ax - mu;
            float p = cc * exp2f(t * t * k2);
            float c = p;
            #pragma unroll
            for (int o = 1; o < 32; o <<= 1) {
                float tt = __shfl_up_sync(FULLMASK, c, o);
                if (lane >= o) c += tt;
            }
            unsigned mm = __ballot_sync(FULLMASK, c > T2);
            if (mm) {
                idx = base_i + sub + (__ffs(mm) - 1);
            } else {
                T2 -= __shfl_sync(FULLMASK, c, 31);
            }
        }
        if (idx < 0) idx = base_i + 63;        // fp drift: crossing at segment end
        if (idx > NSAMP - 1) idx = NSAMP - 1;  // never lands in zero padding
    }

    // ---- Recompute prob at final index (uniform across warp, 1 exp) ----
    float4 q = __ldg(&g_tab[idx >> 1]);
    float ax = (idx & 1) ? q.z : q.x;
    float cc = (idx & 1) ? q.w : q.y;
    float t = ax - mu;
    float p = cc * exp2f(t * t * k2);
    float prob = invnorm * p / denom;

    if (lane == 0) {
        out[row]         = g_grid[idx];  // sampled_values
        out[NROWS + row] = prob;         // sampled_probs
    }
}

extern "C" void kernel_launch(void* const* d_in, const int* in_sizes, int n_in,
                              void* d_out, int out_size) {
    const float* mean = (const float*)d_in[0];
    const float* stdv = (const float*)d_in[1];
    const float* uni  = (const float*)d_in[2];
    float* out = (float*)d_out;

    init_tables_kernel<<<1, 1024>>>();
    sample_kernel<<<NROWS / 8, 256>>>(mean, stdv, uni, out);
}

// round 2
// speedup vs baseline: 5.1062x; 5.1062x over previous
#include <cuda_runtime.h>

#define EPSF     1.1920928955078125e-07f
#define LOG2E    1.4426950408889634f
#define NSAMP    2000
#define NPAD     2048
#define Y0F      0.9999f
#define NROWS    65536
#define FULLMASK 0xffffffffu

// Transposed phase-1 table: g_tabT[j*32 + l] holds points (l*64+2j, l*64+2j+1)
// as (ax0, l2c1_0, ax1, l2c1_1). Coalesced when lane l reads element j.
__device__ float4 g_tabT[NPAD / 2];
// Natural-order table for phase 2: (ax_i, l2c1_i).
__device__ float2 g_tabP[NPAD];
__device__ float  g_grid[NPAD];

__device__ __forceinline__ float ex2(float x) {
    float r;
    asm("ex2.approx.ftz.f32 %0, %1;" : "=f"(r) : "f"(x));
    return r;
}

__global__ void init_tables_kernel() {
    int i = blockIdx.x * blockDim.x + threadIdx.x;  // 0..2047
    if (i >= NPAD) return;
    const float step = 2.0f * Y0F / 1999.0f;
    float ax, l2, g;
    if (i < NSAMP) {
        float x = (i == NSAMP - 1) ? Y0F
                                   : __fadd_rn(__fmul_rn((float)i, step), -Y0F);
        ax = 0.5f * logf((1.0f + x) / (1.0f - x) + EPSF);
        l2 = -log2f(1.0f - x * x);   // log2(1/(1-x^2))
        g  = x;
    } else {
        ax = 0.0f; l2 = -1e30f; g = Y0F;   // exp2(-1e30) == 0: padding contributes nothing
    }
    g_tabP[i] = make_float2(ax, l2);
    g_grid[i] = g;
    // scatter into transposed layout
    int l = i >> 6;            // owning lane
    int j = (i & 63) >> 1;     // iteration
    int h = i & 1;             // half of the float4
    float* ft = (float*)g_tabT;
    ft[(j * 32 + l) * 4 + 2 * h + 0] = ax;
    ft[(j * 32 + l) * 4 + 2 * h + 1] = l2;
}

// One warp per row. Lane l owns contiguous points [64l, 64l+64).
__global__ __launch_bounds__(256, 8) void sample_kernel(
    const float* __restrict__ mean,
    const float* __restrict__ stdv,
    const float* __restrict__ uni,
    float* __restrict__ out)
{
    const int lane = threadIdx.x & 31;
    const int warp = threadIdx.x >> 5;
    const int row  = blockIdx.x * 8 + warp;

    const float mu = __ldg(mean + row);
    const float sg = __ldg(stdv + row) + EPSF;
    const float u  = __ldg(uni + row);
    const float k2 = (-0.5f * LOG2E) / (sg * sg);

    // ---- Phase 1: per-lane segment sums (coalesced transposed loads) ----
    float s0 = 0.0f, s1 = 0.0f;
    const float4* tp = g_tabT + lane;
    #pragma unroll 4
    for (int j = 0; j < 32; ++j) {
        float4 a = __ldg(tp + j * 32);
        float t0 = a.x - mu;
        float t1 = a.z - mu;
        s0 += ex2(__fmaf_rn(t0 * t0, k2, a.y));
        s1 += ex2(__fmaf_rn(t1 * t1, k2, a.w));
    }
    float s = s0 + s1;

    // inclusive warp scan of lane sums
    float incl = s;
    #pragma unroll
    for (int o = 1; o < 32; o <<= 1) {
        float t = __shfl_up_sync(FULLMASK, incl, o);
        if (lane >= o) incl += t;
    }
    const float total = __shfl_sync(FULLMASK, incl, 31);
    const float excl  = incl - s;

    const float invnorm = rsqrtf(6.283185307179586f * sg * sg);
    const float denom   = __fmaf_rn(invnorm, total, EPSF);   // S_norm + EPS
    const float Traw    = u * denom / invnorm;               // threshold in raw space

    // ---- Phase 2: locate crossing segment, then exact index ----
    unsigned m = __ballot_sync(FULLMASK, incl > Traw);
    int idx;
    if (m == 0u) {
        float Snorm = invnorm * total;
        float cl = Snorm / (Snorm + EPSF);       // reference's cdf[last]
        idx = (u < cl) ? (NSAMP - 1) : 0;
    } else {
        const int L = __ffs(m) - 1;
        const float base = __shfl_sync(FULLMASK, excl, L);
        float T2 = Traw - base;
        const int base_i = L * 64;
        idx = -1;
        for (int sub = 0; sub < 64 && idx < 0; sub += 32) {
            int i = base_i + sub + lane;
            float2 q = __ldg(&g_tabP[i]);
            float t = q.x - mu;
            float p = ex2(__fmaf_rn(t * t, k2, q.y));
            float c = p;
            #pragma unroll
            for (int o = 1; o < 32; o <<= 1) {
                float tt = __shfl_up_sync(FULLMASK, c, o);
                if (lane >= o) c += tt;
            }
            unsigned mm = __ballot_sync(FULLMASK, c > T2);
            if (mm) {
                idx = base_i + sub + (__ffs(mm) - 1);
            } else {
                T2 -= __shfl_sync(FULLMASK, c, 31);
            }
        }
        if (idx < 0) idx = base_i + 63;        // fp drift: crossing at segment end
        if (idx > NSAMP - 1) idx = NSAMP - 1;
    }

    // ---- Recompute prob at final index ----
    float2 q = __ldg(&g_tabP[idx]);
    float t = q.x - mu;
    float p = ex2(__fmaf_rn(t * t, k2, q.y));
    float prob = invnorm * p / denom;

    if (lane == 0) {
        out[row]         = g_grid[idx];  // sampled_values
        out[NROWS + row] = prob;         // sampled_probs
    }
}

extern "C" void kernel_launch(void* const* d_in, const int* in_sizes, int n_in,
                              void* d_out, int out_size) {
    const float* mean = (const float*)d_in[0];
    const float* stdv = (const float*)d_in[1];
    const float* uni  = (const float*)d_in[2];
    float* out = (float*)d_out;

    init_tables_kernel<<<2, 1024>>>();
    sample_kernel<<<NROWS / 8, 256>>>(mean, stdv, uni, out);
}